// round 13
// baseline (speedup 1.0000x reference)
#include <cuda_runtime.h>
#include <cuda_bf16.h>
#include <cstdint>

#define BB 2
#define LL 8192
#define DMM 256
#define NHH 4
#define HPP 64
#define NSS 8
#define DINN 256
#define DPROJ 532
#define NPROJ2 1064
#define QC 128
#define SUBC 64
#define NCHUNK 64
#define NUNIT 32
#define MM (BB*LL)

#define AXSZ ((size_t)MM*DMM)
#define ZXSZ ((size_t)MM*NPROJ2)
#define YSZ  ((size_t)MM*DINN)
#define WISZ ((size_t)1152*256)
#define WOSZ ((size_t)256*256)
#define WFSZ ((size_t)256*1024)

// ---------------- device scratch ----------------
__device__ float g_zx[2*ZXSZ];
__device__ __nv_bfloat16 g_ax_hi[2*AXSZ], g_ax_lo[2*AXSZ];
__device__ __nv_bfloat16 g_y_hi[4*YSZ],  g_y_lo[4*YSZ];
__device__ __nv_bfloat16 g_cat_hi[(size_t)MM*1024], g_cat_lo[(size_t)MM*1024];
__device__ __nv_bfloat16 g_wi_hi[2*WISZ], g_wi_lo[2*WISZ];
__device__ __nv_bfloat16 g_wo_hi[4*WOSZ], g_wo_lo[4*WOSZ];
__device__ __nv_bfloat16 g_wf_hi[WFSZ],   g_wf_lo[WFSZ];
__device__ float g_cstate[(size_t)NUNIT*NCHUNK*HPP*NSS];
__device__ float g_istate[(size_t)NUNIT*NCHUNK*HPP*NSS];
__device__ float g_cdecay[NUNIT*NCHUNK];

// ---------------- helpers ----------------
__device__ __forceinline__ float siluf(float x) { return x / (1.f + __expf(-x)); }
__device__ __forceinline__ float softplusf(float x) {
    return fmaxf(x, 0.f) + log1pf(__expf(-fabsf(x)));
}
__device__ __forceinline__ void split_bf16(float v, __nv_bfloat16& hi, __nv_bfloat16& lo) {
    hi = __float2bfloat16(v);
    lo = __float2bfloat16(v - __bfloat162float(hi));
}

#define MMA_BF16(d, a0,a1,a2,a3, b0,b1) \
    asm volatile("mma.sync.aligned.m16n8k16.row.col.f32.bf16.bf16.f32 " \
        "{%0,%1,%2,%3}, {%4,%5,%6,%7}, {%8,%9}, {%0,%1,%2,%3};" \
        : "+f"(d[0]),"+f"(d[1]),"+f"(d[2]),"+f"(d[3]) \
        : "r"(a0),"r"(a1),"r"(a2),"r"(a3), "r"(b0),"r"(b1))

// ---------------- prep kernels ----------------
__global__ void conv_split(const float* __restrict__ src, int sel) {
    size_t i = ((size_t)blockIdx.x * blockDim.x + threadIdx.x) * 4;
    if (i >= AXSZ) return;
    float4 v = *(const float4*)(src + i);
    __nv_bfloat16* ph = g_ax_hi + (size_t)sel * AXSZ + i;
    __nv_bfloat16* pl = g_ax_lo + (size_t)sel * AXSZ + i;
    float a[4] = {v.x, v.y, v.z, v.w};
#pragma unroll
    for (int j = 0; j < 4; j++) { __nv_bfloat16 h, l; split_bf16(a[j], h, l); ph[j] = h; pl[j] = l; }
}

// transpose W[K,N] -> Wt[Npad,K] split hi/lo (zero pad rows)
__global__ void wsplit(const float* __restrict__ W, int which, int sub, int K, int N, int Npad) {
    int idx = blockIdx.x * blockDim.x + threadIdx.x;
    if (idx >= Npad * K) return;
    int n = idx / K, k = idx - n * K;
    float v = (n < N) ? W[(size_t)k * N + n] : 0.f;
    __nv_bfloat16 h, l; split_bf16(v, h, l);
    __nv_bfloat16 *dh, *dl;
    if (which == 0) { dh = g_wi_hi + (size_t)sub * WISZ; dl = g_wi_lo + (size_t)sub * WISZ; }
    else if (which == 1) { dh = g_wo_hi + (size_t)sub * WOSZ; dl = g_wo_lo + (size_t)sub * WOSZ; }
    else { dh = g_wf_hi; dl = g_wf_lo; }
    dh[idx] = h; dl[idx] = l;
}

// ---------------- split-bf16 mma.sync GEMM ----------------
// CTA tile 128x128, 8 warps (4 M x 2 N), warp tile 32x64, K-tile 32.
// MODE 0: A=g_ax[z], B=g_wi[z],   K=256,  N=1064 -> g_zx fp32 (silu/softplus)
// MODE 1: A=g_y[z],  B=g_wo[z^1], K=256,  N=256  -> g_cat hi/lo (silu, scatter z>=2)
// MODE 2: A=g_cat,   B=g_wf,      K=1024, N=256  -> Cext fp32
#define SSTR 40   // smem row stride in bf16 (32 data + 8 pad)
template <int MODE>
__global__ __launch_bounds__(256) void gemm_mma(
    float* __restrict__ Cext,
    const float* __restrict__ dtbH0, const float* __restrict__ dtbH1,
    const float* __restrict__ dtbV0, const float* __restrict__ dtbV1,
    const int* __restrict__ rowmap)
{
    __shared__ __nv_bfloat16 Ash[128*SSTR], Als[128*SSTR];
    __shared__ __nv_bfloat16 Bsh[128*SSTR], Bls[128*SSTR];

    const int K = (MODE == 2) ? 1024 : 256;
    int tid = threadIdx.x, lane = tid & 31, wid = tid >> 5;
    int warp_m = wid & 3, warp_n = wid >> 2;
    int qr = lane >> 2, qc = lane & 3;
    int bn = blockIdx.x, bm = blockIdx.y, z = blockIdx.z;

    const __nv_bfloat16 *Ah, *Al, *Bh, *Bl;
    if (MODE == 0) {
        Ah = g_ax_hi + (size_t)z * AXSZ; Al = g_ax_lo + (size_t)z * AXSZ;
        Bh = g_wi_hi + (size_t)z * WISZ; Bl = g_wi_lo + (size_t)z * WISZ;
    } else if (MODE == 1) {
        Ah = g_y_hi + (size_t)z * YSZ;   Al = g_y_lo + (size_t)z * YSZ;
        int bs = z ^ 1;   // reference swaps F/B output weights
        Bh = g_wo_hi + (size_t)bs * WOSZ; Bl = g_wo_lo + (size_t)bs * WOSZ;
    } else {
        Ah = g_cat_hi; Al = g_cat_lo; Bh = g_wf_hi; Bl = g_wf_lo;
    }

    // gmem->smem mapping: thread loads 32 contiguous bf16 per array per K-tile
    int lrow = tid >> 1;
    int lhalf = (tid & 1) << 4;               // 0 or 16 elems
    size_t aoff = (size_t)(bm * 128 + lrow) * K + lhalf;
    size_t boff = (size_t)(bn * 128 + lrow) * K + lhalf;
    int soff = lrow * SSTR + lhalf;

    float acc[2][8][4];
#pragma unroll
    for (int i = 0; i < 2; i++)
#pragma unroll
        for (int j = 0; j < 8; j++)
#pragma unroll
            for (int k = 0; k < 4; k++) acc[i][j][k] = 0.f;

    uint4 pah0, pah1, pal0, pal1, pbh0, pbh1, pbl0, pbl1;
    pah0 = *(const uint4*)(Ah + aoff);     pah1 = *(const uint4*)(Ah + aoff + 8);
    pal0 = *(const uint4*)(Al + aoff);     pal1 = *(const uint4*)(Al + aoff + 8);
    pbh0 = *(const uint4*)(Bh + boff);     pbh1 = *(const uint4*)(Bh + boff + 8);
    pbl0 = *(const uint4*)(Bl + boff);     pbl1 = *(const uint4*)(Bl + boff + 8);

    const int nk = K >> 5;
    for (int kt = 0; kt < nk; kt++) {
        *(uint4*)&Ash[soff] = pah0;  *(uint4*)&Ash[soff + 8] = pah1;
        *(uint4*)&Als[soff] = pal0;  *(uint4*)&Als[soff + 8] = pal1;
        *(uint4*)&Bsh[soff] = pbh0;  *(uint4*)&Bsh[soff + 8] = pbh1;
        *(uint4*)&Bls[soff] = pbl0;  *(uint4*)&Bls[soff + 8] = pbl1;
        __syncthreads();
        if (kt + 1 < nk) {
            size_t ao = aoff + (size_t)(kt + 1) * 32;
            size_t bo = boff + (size_t)(kt + 1) * 32;
            pah0 = *(const uint4*)(Ah + ao);  pah1 = *(const uint4*)(Ah + ao + 8);
            pal0 = *(const uint4*)(Al + ao);  pal1 = *(const uint4*)(Al + ao + 8);
            pbh0 = *(const uint4*)(Bh + bo);  pbh1 = *(const uint4*)(Bh + bo + 8);
            pbl0 = *(const uint4*)(Bl + bo);  pbl1 = *(const uint4*)(Bl + bo + 8);
        }
#pragma unroll
        for (int ks = 0; ks < 2; ks++) {
            int kof = ks * 16 + qc * 2;
            uint32_t bhf[8][2], blf[8][2];
#pragma unroll
            for (int nt = 0; nt < 8; nt++) {
                int nr = (warp_n * 64 + nt * 8 + qr) * SSTR + kof;
                bhf[nt][0] = *(const uint32_t*)&Bsh[nr];
                bhf[nt][1] = *(const uint32_t*)&Bsh[nr + 8];
                blf[nt][0] = *(const uint32_t*)&Bls[nr];
                blf[nt][1] = *(const uint32_t*)&Bls[nr + 8];
            }
#pragma unroll
            for (int mt = 0; mt < 2; mt++) {
                int ar = (warp_m * 32 + mt * 16 + qr) * SSTR + kof;
                uint32_t ah0 = *(const uint32_t*)&Ash[ar];
                uint32_t ah1 = *(const uint32_t*)&Ash[ar + 8 * SSTR];
                uint32_t ah2 = *(const uint32_t*)&Ash[ar + 8];
                uint32_t ah3 = *(const uint32_t*)&Ash[ar + 8 * SSTR + 8];
                uint32_t al0 = *(const uint32_t*)&Als[ar];
                uint32_t al1 = *(const uint32_t*)&Als[ar + 8 * SSTR];
                uint32_t al2 = *(const uint32_t*)&Als[ar + 8];
                uint32_t al3 = *(const uint32_t*)&Als[ar + 8 * SSTR + 8];
#pragma unroll
                for (int nt = 0; nt < 8; nt++) {
                    MMA_BF16(acc[mt][nt], ah0, ah1, ah2, ah3, bhf[nt][0], bhf[nt][1]);
                    MMA_BF16(acc[mt][nt], ah0, ah1, ah2, ah3, blf[nt][0], blf[nt][1]);
                    MMA_BF16(acc[mt][nt], al0, al1, al2, al3, bhf[nt][0], bhf[nt][1]);
                }
            }
        }
        __syncthreads();
    }

    // ---------------- epilogue ----------------
#pragma unroll
    for (int mt = 0; mt < 2; mt++) {
        int r0 = bm * 128 + warp_m * 32 + mt * 16 + qr;
#pragma unroll
        for (int nt = 0; nt < 8; nt++) {
            int c = bn * 128 + warp_n * 64 + nt * 8 + qc * 2;
            const float* a = acc[mt][nt];
#pragma unroll
            for (int rr = 0; rr < 2; rr++) {
                int r = r0 + rr * 8;
                float v0 = a[rr * 2 + 0], v1 = a[rr * 2 + 1];
                if (MODE == 0) {
                    float* C = g_zx + (size_t)z * ZXSZ + (size_t)r * NPROJ2;
                    float vv[2] = {v0, v1};
#pragma unroll
                    for (int h = 0; h < 2; h++) {
                        int cc = c + h;
                        if (cc < NPROJ2) {
                            int dI = (cc >= DPROJ);
                            int rI = cc - dI * DPROJ;
                            float o;
                            if (rI < 2 * DINN + 2 * NSS) o = siluf(vv[h]);
                            else {
                                const float* dtb = z ? (dI ? dtbV1 : dtbV0)
                                                     : (dI ? dtbH1 : dtbH0);
                                o = softplusf(vv[h] + dtb[rI - (2 * DINN + 2 * NSS)]);
                            }
                            C[cc] = o;
                        }
                    }
                } else if (MODE == 1) {
                    int orow = r;
                    if (z >= 2) orow = (r & ~(LL - 1)) | rowmap[r];
                    size_t rb = (size_t)orow * 1024 + z * 256 + c;
                    float o0 = siluf(v0), o1 = siluf(v1);
                    __nv_bfloat16 h0, l0, h1, l1;
                    split_bf16(o0, h0, l0); split_bf16(o1, h1, l1);
                    __nv_bfloat162 ph; ph.x = h0; ph.y = h1;
                    __nv_bfloat162 pl; pl.x = l0; pl.y = l1;
                    *(__nv_bfloat162*)&g_cat_hi[rb] = ph;
                    *(__nv_bfloat162*)&g_cat_lo[rb] = pl;
                } else {
                    float2 o; o.x = v0; o.y = v1;
                    *(float2*)&Cext[(size_t)r * 256 + c] = o;
                }
            }
        }
    }
}

// ---------------- scan kernels ----------------
struct SP { const float* alog[4]; const float* Dp[4]; };

__global__ __launch_bounds__(64) void scan_pass1(SP sp)
{
    __shared__ float bc[QC][20];
    __shared__ float xs[SUBC][HPP];

    int chunk = blockIdx.x;
    int b = blockIdx.y >> 2, head = blockIdx.y & 3, dir = blockIdx.z;
    int tid = threadIdx.x;

    const float* base = g_zx + (size_t)(dir >> 1) * ZXSZ;
    int off = (dir & 1) * DPROJ;
    bool rev = (dir & 1);
    long t0 = rev ? (long)(LL - 1 - chunk * QC) : (long)(chunk * QC);
    long rstride = rev ? -(long)NPROJ2 : (long)NPROJ2;
    const float* row0 = base + ((long)b * LL + t0) * NPROJ2 + off;

    for (int idx = tid; idx < QC * 20; idx += 64) {
        int st = idx / 20, q = idx - st * 20;
        bc[st][q] = row0[(long)st * rstride + 2 * DINN + q];
    }

    float a = -__expf(sp.alog[dir][head]);
    float s[NSS];
#pragma unroll
    for (int n = 0; n < NSS; n++) s[n] = 0.f;
    float Pd = 1.f;

    const float* xbase = row0 + DINN + head * HPP;
    for (int sub = 0; sub < QC; sub += SUBC) {
        __syncthreads();
        for (int idx = tid; idx < SUBC * 16; idx += 64) {
            int st = idx >> 4, v = (idx & 15) * 4;
            *(float4*)&xs[st][v] = *(const float4*)(xbase + (long)(sub + st) * rstride + v);
        }
        __syncthreads();
        for (int st = 0; st < SUBC; st++) {
            int t = sub + st;
            float dt = bc[t][16 + head];
            float dA = __expf(dt * a);
            float dtx = dt * xs[st][tid];
            Pd *= dA;
            float4 b0 = *(const float4*)&bc[t][0];
            float4 b1 = *(const float4*)&bc[t][4];
            s[0] = fmaf(dA, s[0], b0.x * dtx);
            s[1] = fmaf(dA, s[1], b0.y * dtx);
            s[2] = fmaf(dA, s[2], b0.z * dtx);
            s[3] = fmaf(dA, s[3], b0.w * dtx);
            s[4] = fmaf(dA, s[4], b1.x * dtx);
            s[5] = fmaf(dA, s[5], b1.y * dtx);
            s[6] = fmaf(dA, s[6], b1.z * dtx);
            s[7] = fmaf(dA, s[7], b1.w * dtx);
        }
    }

    int u = (dir * BB + b) * NHH + head;
    size_t sb = ((size_t)u * NCHUNK + chunk) * (HPP * NSS) + (size_t)tid * NSS;
#pragma unroll
    for (int n = 0; n < NSS; n++) g_cstate[sb + n] = s[n];
    if (tid == 0) g_cdecay[u * NCHUNK + chunk] = Pd;
}

__global__ __launch_bounds__(512) void scan_pass2()
{
    __shared__ float dec[NCHUNK];
    int u = blockIdx.x, tid = threadIdx.x;
    if (tid < NCHUNK) dec[tid] = g_cdecay[u * NCHUNK + tid];
    __syncthreads();
    float h = 0.f;
    size_t base = (size_t)u * NCHUNK * (HPP * NSS) + tid;
    for (int cb = 0; cb < NCHUNK / 8; cb++) {
        float v[8];
#pragma unroll
        for (int j = 0; j < 8; j++)
            v[j] = g_cstate[base + (size_t)(cb * 8 + j) * (HPP * NSS)];
#pragma unroll
        for (int j = 0; j < 8; j++) {
            size_t idx = base + (size_t)(cb * 8 + j) * (HPP * NSS);
            g_istate[idx] = h;
            h = dec[cb * 8 + j] * h + v[j];
        }
    }
}

__global__ __launch_bounds__(64) void scan_pass3(SP sp)
{
    __shared__ float bc[QC][20];
    __shared__ float xs[SUBC][HPP];
    __shared__ float zs[SUBC][HPP];

    int chunk = blockIdx.x;
    int b = blockIdx.y >> 2, head = blockIdx.y & 3, dir = blockIdx.z;
    int tid = threadIdx.x;

    const float* base = g_zx + (size_t)(dir >> 1) * ZXSZ;
    int off = (dir & 1) * DPROJ;
    bool rev = (dir & 1);
    long t0 = rev ? (long)(LL - 1 - chunk * QC) : (long)(chunk * QC);
    long rstride = rev ? -(long)NPROJ2 : (long)NPROJ2;
    const float* row0 = base + ((long)b * LL + t0) * NPROJ2 + off;

    for (int idx = tid; idx < QC * 20; idx += 64) {
        int st = idx / 20, q = idx - st * 20;
        bc[st][q] = row0[(long)st * rstride + 2 * DINN + q];
    }

    float a = -__expf(sp.alog[dir][head]);
    float Dh = sp.Dp[dir][head];

    int u = (dir * BB + b) * NHH + head;
    size_t sb = ((size_t)u * NCHUNK + chunk) * (HPP * NSS) + (size_t)tid * NSS;
    float s[NSS];
#pragma unroll
    for (int n = 0; n < NSS; n++) s[n] = g_istate[sb + n];

    size_t ybase = (size_t)dir * YSZ + ((size_t)b * LL + (size_t)t0) * DINN + head * HPP + tid;
    long ystride = rev ? -(long)DINN : (long)DINN;

    const float* xbase = row0 + DINN + head * HPP;
    const float* zbase = row0 + head * HPP;

    for (int sub = 0; sub < QC; sub += SUBC) {
        __syncthreads();
        for (int idx = tid; idx < SUBC * 16; idx += 64) {
            int st = idx >> 4, v = (idx & 15) * 4;
            *(float4*)&xs[st][v] = *(const float4*)(xbase + (long)(sub + st) * rstride + v);
            *(float4*)&zs[st][v] = *(const float4*)(zbase + (long)(sub + st) * rstride + v);
        }
        __syncthreads();
        for (int st = 0; st < SUBC; st++) {
            int t = sub + st;
            float dt = bc[t][16 + head];
            float dA = __expf(dt * a);
            float xv = xs[st][tid];
            float dtx = dt * xv;
            float4 b0 = *(const float4*)&bc[t][0];
            float4 b1 = *(const float4*)&bc[t][4];
            float4 c0 = *(const float4*)&bc[t][8];
            float4 c1 = *(const float4*)&bc[t][12];
            s[0] = fmaf(dA, s[0], b0.x * dtx);
            s[1] = fmaf(dA, s[1], b0.y * dtx);
            s[2] = fmaf(dA, s[2], b0.z * dtx);
            s[3] = fmaf(dA, s[3], b0.w * dtx);
            s[4] = fmaf(dA, s[4], b1.x * dtx);
            s[5] = fmaf(dA, s[5], b1.y * dtx);
            s[6] = fmaf(dA, s[6], b1.z * dtx);
            s[7] = fmaf(dA, s[7], b1.w * dtx);
            float y0 = fmaf(s[0], c0.x, fmaf(s[2], c0.z, fmaf(s[4], c1.x, s[6] * c1.z)));
            float y1 = fmaf(s[1], c0.y, fmaf(s[3], c0.w, fmaf(s[5], c1.y, s[7] * c1.w)));
            float outv = fmaf(Dh, xv, y0 + y1) * zs[st][tid];
            __nv_bfloat16 h, l; split_bf16(outv, h, l);
            size_t yo = ybase + (long)t * ystride;
            g_y_hi[yo] = h;
            g_y_lo[yo] = l;
        }
    }
}

// ---------------- launch ----------------
extern "C" void kernel_launch(void* const* d_in, const int* in_sizes, int n_in,
                              void* d_out, int out_size)
{
    const float *xH, *xV, *WinH, *WinV, *WoHF, *WoHB, *WoVF, *WoVB, *Wout;
    const float *dtb[4], *alog[4], *Dp[4];
    const int* v2h;

    if (in_sizes[0] == 4) {
        alog[1] = (const float*)d_in[0];  alog[0] = (const float*)d_in[1];
        alog[3] = (const float*)d_in[2];  alog[2] = (const float*)d_in[3];
        Dp[1]   = (const float*)d_in[4];  Dp[0]   = (const float*)d_in[5];
        Dp[3]   = (const float*)d_in[6];  Dp[2]   = (const float*)d_in[7];
        WinH = (const float*)d_in[8];     WinV = (const float*)d_in[9];
        Wout = (const float*)d_in[10];
        WoHB = (const float*)d_in[11];    WoHF = (const float*)d_in[12];
        WoVB = (const float*)d_in[13];    WoVF = (const float*)d_in[14];
        dtb[1] = (const float*)d_in[15];  dtb[0] = (const float*)d_in[16];
        dtb[3] = (const float*)d_in[17];  dtb[2] = (const float*)d_in[18];
        v2h = (const int*)d_in[19];
        xH = (const float*)d_in[20];      xV = (const float*)d_in[21];
    } else if (in_sizes[4] == 65536) {
        xH = (const float*)d_in[0];  xV = (const float*)d_in[1];
        WinH = (const float*)d_in[2]; WinV = (const float*)d_in[3];
        WoHF = (const float*)d_in[4]; WoHB = (const float*)d_in[5];
        WoVF = (const float*)d_in[6]; WoVB = (const float*)d_in[7];
        Wout = (const float*)d_in[8];
        for (int d = 0; d < 4; d++) {
            dtb[d]  = (const float*)d_in[9 + 3 * d + 0];
            alog[d] = (const float*)d_in[9 + 3 * d + 1];
            Dp[d]   = (const float*)d_in[9 + 3 * d + 2];
        }
        v2h = (const int*)d_in[21];
    } else {
        xH = (const float*)d_in[0];  xV = (const float*)d_in[1];
        WinH = (const float*)d_in[2]; WinV = (const float*)d_in[3];
        for (int d = 0; d < 4; d++) {
            dtb[d]  = (const float*)d_in[4 + d];
            alog[d] = (const float*)d_in[8 + d];
            Dp[d]   = (const float*)d_in[12 + d];
        }
        WoHF = (const float*)d_in[16]; WoHB = (const float*)d_in[17];
        WoVF = (const float*)d_in[18]; WoVB = (const float*)d_in[19];
        Wout = (const float*)d_in[20];
        v2h = (const int*)d_in[21];
    }

    SP sp;
    for (int d = 0; d < 4; d++) { sp.alog[d] = alog[d]; sp.Dp[d] = Dp[d]; }

    // prep: split inputs + transpose/split weights
    conv_split<<<(int)(AXSZ / 4 / 256), 256>>>(xH, 0);
    conv_split<<<(int)(AXSZ / 4 / 256), 256>>>(xV, 1);
    wsplit<<<1152, 256>>>(WinH, 0, 0, 256, NPROJ2, 1152);
    wsplit<<<1152, 256>>>(WinV, 0, 1, 256, NPROJ2, 1152);
    wsplit<<<256, 256>>>(WoHF, 1, 0, 256, 256, 256);
    wsplit<<<256, 256>>>(WoHB, 1, 1, 256, 256, 256);
    wsplit<<<256, 256>>>(WoVF, 1, 2, 256, 256, 256);
    wsplit<<<256, 256>>>(WoVB, 1, 3, 256, 256, 256);
    wsplit<<<1024, 256>>>(Wout, 2, 0, 1024, 256, 256);

    // in-proj (both H and V batched via z) + fused activations
    gemm_mma<0><<<dim3(9, MM / 128, 2), 256>>>(
        nullptr, dtb[0], dtb[1], dtb[2], dtb[3], nullptr);

    // chunked selective scan
    scan_pass1<<<dim3(NCHUNK, BB * NHH, 4), 64>>>(sp);
    scan_pass2<<<NUNIT, 512>>>();
    scan_pass3<<<dim3(NCHUNK, BB * NHH, 4), 64>>>(sp);

    // out-projections (all 4 dirs batched via z): silu + v2h scatter -> cat hi/lo
    gemm_mma<1><<<dim3(2, MM / 128, 4), 256>>>(
        nullptr, nullptr, nullptr, nullptr, nullptr, v2h);

    // final projection
    gemm_mma<2><<<dim3(2, MM / 128, 1), 256>>>(
        (float*)d_out, nullptr, nullptr, nullptr, nullptr, nullptr);
}

// round 14
// speedup vs baseline: 1.3018x; 1.3018x over previous
#include <cuda_runtime.h>
#include <cuda_bf16.h>
#include <cstdint>

#define BB 2
#define LL 8192
#define DMM 256
#define NHH 4
#define HPP 64
#define NSS 8
#define DINN 256
#define DPROJ 532
#define NPROJ2 1064
#define QC 128
#define SUBC 64
#define NCHUNK 64
#define NUNIT 32
#define MM (BB*LL)

#define AXSZ ((size_t)MM*DMM)
#define ZXSZ ((size_t)MM*NPROJ2)
#define YSZ  ((size_t)MM*DINN)
#define WISZ ((size_t)1152*256)
#define WOSZ ((size_t)256*256)
#define WFSZ ((size_t)256*1024)

// ---------------- device scratch ----------------
__device__ float g_zx[2*ZXSZ];
__device__ __nv_bfloat16 g_ax_hi[2*AXSZ], g_ax_lo[2*AXSZ];
__device__ __nv_bfloat16 g_y_hi[4*YSZ],  g_y_lo[4*YSZ];
__device__ __nv_bfloat16 g_cat_hi[(size_t)MM*1024], g_cat_lo[(size_t)MM*1024];
__device__ __nv_bfloat16 g_wi_hi[2*WISZ], g_wi_lo[2*WISZ];
__device__ __nv_bfloat16 g_wo_hi[4*WOSZ], g_wo_lo[4*WOSZ];
__device__ __nv_bfloat16 g_wf_hi[WFSZ],   g_wf_lo[WFSZ];
__device__ float g_cstate[(size_t)NUNIT*NCHUNK*HPP*NSS];
__device__ float g_istate[(size_t)NUNIT*NCHUNK*HPP*NSS];
__device__ float g_cdecay[NUNIT*NCHUNK];

// ---------------- helpers ----------------
__device__ __forceinline__ float siluf(float x) { return x / (1.f + __expf(-x)); }
__device__ __forceinline__ float softplusf(float x) {
    return fmaxf(x, 0.f) + log1pf(__expf(-fabsf(x)));
}
__device__ __forceinline__ void split_bf16(float v, __nv_bfloat16& hi, __nv_bfloat16& lo) {
    hi = __float2bfloat16(v);
    lo = __float2bfloat16(v - __bfloat162float(hi));
}

#define MMA_BF16(d, a0,a1,a2,a3, b0,b1) \
    asm volatile("mma.sync.aligned.m16n8k16.row.col.f32.bf16.bf16.f32 " \
        "{%0,%1,%2,%3}, {%4,%5,%6,%7}, {%8,%9}, {%0,%1,%2,%3};" \
        : "+f"(d[0]),"+f"(d[1]),"+f"(d[2]),"+f"(d[3]) \
        : "r"(a0),"r"(a1),"r"(a2),"r"(a3), "r"(b0),"r"(b1))

__device__ __forceinline__ void cp16(uint32_t saddr, const void* g) {
    asm volatile("cp.async.cg.shared.global [%0], [%1], 16;" :: "r"(saddr), "l"(g));
}
__device__ __forceinline__ void cpcommit() {
    asm volatile("cp.async.commit_group;" ::: "memory");
}
__device__ __forceinline__ void cpwait0() {
    asm volatile("cp.async.wait_group 0;" ::: "memory");
}

// ---------------- prep kernels ----------------
__global__ void conv_split(const float* __restrict__ src, int sel) {
    size_t i = ((size_t)blockIdx.x * blockDim.x + threadIdx.x) * 4;
    if (i >= AXSZ) return;
    float4 v = *(const float4*)(src + i);
    __nv_bfloat16* ph = g_ax_hi + (size_t)sel * AXSZ + i;
    __nv_bfloat16* pl = g_ax_lo + (size_t)sel * AXSZ + i;
    float a[4] = {v.x, v.y, v.z, v.w};
#pragma unroll
    for (int j = 0; j < 4; j++) { __nv_bfloat16 h, l; split_bf16(a[j], h, l); ph[j] = h; pl[j] = l; }
}

// transpose W[K,N] -> Wt[Npad,K] split hi/lo (zero pad rows)
__global__ void wsplit(const float* __restrict__ W, int which, int sub, int K, int N, int Npad) {
    int idx = blockIdx.x * blockDim.x + threadIdx.x;
    if (idx >= Npad * K) return;
    int n = idx / K, k = idx - n * K;
    float v = (n < N) ? W[(size_t)k * N + n] : 0.f;
    __nv_bfloat16 h, l; split_bf16(v, h, l);
    __nv_bfloat16 *dh, *dl;
    if (which == 0) { dh = g_wi_hi + (size_t)sub * WISZ; dl = g_wi_lo + (size_t)sub * WISZ; }
    else if (which == 1) { dh = g_wo_hi + (size_t)sub * WOSZ; dl = g_wo_lo + (size_t)sub * WOSZ; }
    else { dh = g_wf_hi; dl = g_wf_lo; }
    dh[idx] = h; dl[idx] = l;
}

// ---------------- split-bf16 mma.sync GEMM, cp.async 2-stage ----------------
// CTA tile 128x128, 8 warps (4 M x 2 N), warp tile 32x64, K-tile 32.
// MODE 0: A=g_ax[z], B=g_wi[z],   K=256,  N=1064 -> g_zx fp32 (silu/softplus)
// MODE 1: A=g_y[z],  B=g_wo[z^1], K=256,  N=256  -> g_cat hi/lo (silu, scatter z>=2)
// MODE 2: A=g_cat,   B=g_wf,      K=1024, N=256  -> Cext fp32
#define SSTR 40             // smem row stride in bf16 (32 data + 8 pad)
#define SARR (128*SSTR)     // elems per array (5120)
#define SARRB (SARR*2)      // bytes per array (10240)
#define STGB (4*SARRB)      // bytes per stage (40960)
#define GSMEM (2*STGB)      // 81920 bytes dynamic smem
template <int MODE>
__global__ __launch_bounds__(256, 2) void gemm_mma(
    float* __restrict__ Cext,
    const float* __restrict__ dtbH0, const float* __restrict__ dtbH1,
    const float* __restrict__ dtbV0, const float* __restrict__ dtbV1,
    const int* __restrict__ rowmap)
{
    extern __shared__ __align__(16) __nv_bfloat16 sm[];

    const int K = (MODE == 2) ? 1024 : 256;
    int tid = threadIdx.x, lane = tid & 31, wid = tid >> 5;
    int warp_m = wid & 3, warp_n = wid >> 2;
    int qr = lane >> 2, qc = lane & 3;
    int bn = blockIdx.x, bm = blockIdx.y, z = blockIdx.z;

    const __nv_bfloat16 *Ah, *Al, *Bh, *Bl;
    if (MODE == 0) {
        Ah = g_ax_hi + (size_t)z * AXSZ; Al = g_ax_lo + (size_t)z * AXSZ;
        Bh = g_wi_hi + (size_t)z * WISZ; Bl = g_wi_lo + (size_t)z * WISZ;
    } else if (MODE == 1) {
        Ah = g_y_hi + (size_t)z * YSZ;   Al = g_y_lo + (size_t)z * YSZ;
        int bs = z ^ 1;   // reference swaps F/B output weights
        Bh = g_wo_hi + (size_t)bs * WOSZ; Bl = g_wo_lo + (size_t)bs * WOSZ;
    } else {
        Ah = g_cat_hi; Al = g_cat_lo; Bh = g_wf_hi; Bl = g_wf_lo;
    }

    // gmem->smem: each thread owns 16 contiguous bf16 per array per K-tile
    int lrow = tid >> 1;
    int lhalf = (tid & 1) << 4;
    size_t aoff = (size_t)(bm * 128 + lrow) * K + lhalf;
    size_t boff = (size_t)(bn * 128 + lrow) * K + lhalf;
    int soffB = (lrow * SSTR + lhalf) * 2;     // byte offset within array
    uint32_t sbu = (uint32_t)__cvta_generic_to_shared(sm);

    float acc[2][8][4];
#pragma unroll
    for (int i = 0; i < 2; i++)
#pragma unroll
        for (int j = 0; j < 8; j++)
#pragma unroll
            for (int k = 0; k < 4; k++) acc[i][j][k] = 0.f;

    const int nk = K >> 5;

    // prologue: stage 0
    {
        uint32_t st = sbu;
        cp16(st + 0*SARRB + soffB,      Ah + aoff);
        cp16(st + 0*SARRB + soffB + 16, Ah + aoff + 8);
        cp16(st + 1*SARRB + soffB,      Al + aoff);
        cp16(st + 1*SARRB + soffB + 16, Al + aoff + 8);
        cp16(st + 2*SARRB + soffB,      Bh + boff);
        cp16(st + 2*SARRB + soffB + 16, Bh + boff + 8);
        cp16(st + 3*SARRB + soffB,      Bl + boff);
        cp16(st + 3*SARRB + soffB + 16, Bl + boff + 8);
        cpcommit();
    }

    for (int kt = 0; kt < nk; kt++) {
        int s = kt & 1;
        cpwait0();
        __syncthreads();
        if (kt + 1 < nk) {
            uint32_t st = sbu + (s ^ 1) * STGB;
            size_t ka = aoff + (size_t)(kt + 1) * 32;
            size_t kb = boff + (size_t)(kt + 1) * 32;
            cp16(st + 0*SARRB + soffB,      Ah + ka);
            cp16(st + 0*SARRB + soffB + 16, Ah + ka + 8);
            cp16(st + 1*SARRB + soffB,      Al + ka);
            cp16(st + 1*SARRB + soffB + 16, Al + ka + 8);
            cp16(st + 2*SARRB + soffB,      Bh + kb);
            cp16(st + 2*SARRB + soffB + 16, Bh + kb + 8);
            cp16(st + 3*SARRB + soffB,      Bl + kb);
            cp16(st + 3*SARRB + soffB + 16, Bl + kb + 8);
            cpcommit();
        }
        const __nv_bfloat16* As  = sm + s * (STGB/2) + 0*SARR;
        const __nv_bfloat16* Als = sm + s * (STGB/2) + 1*SARR;
        const __nv_bfloat16* Bs  = sm + s * (STGB/2) + 2*SARR;
        const __nv_bfloat16* Bls = sm + s * (STGB/2) + 3*SARR;

#pragma unroll
        for (int ks = 0; ks < 2; ks++) {
            int kof = ks * 16 + qc * 2;
            uint32_t ah[2][4], al[2][4];
#pragma unroll
            for (int mt = 0; mt < 2; mt++) {
                int ar = (warp_m * 32 + mt * 16 + qr) * SSTR + kof;
                ah[mt][0] = *(const uint32_t*)&As[ar];
                ah[mt][1] = *(const uint32_t*)&As[ar + 8 * SSTR];
                ah[mt][2] = *(const uint32_t*)&As[ar + 8];
                ah[mt][3] = *(const uint32_t*)&As[ar + 8 * SSTR + 8];
                al[mt][0] = *(const uint32_t*)&Als[ar];
                al[mt][1] = *(const uint32_t*)&Als[ar + 8 * SSTR];
                al[mt][2] = *(const uint32_t*)&Als[ar + 8];
                al[mt][3] = *(const uint32_t*)&Als[ar + 8 * SSTR + 8];
            }
#pragma unroll
            for (int g = 0; g < 2; g++) {
                uint32_t bh[4][2], bl[4][2];
#pragma unroll
                for (int j = 0; j < 4; j++) {
                    int nr = (warp_n * 64 + (g * 4 + j) * 8 + qr) * SSTR + kof;
                    bh[j][0] = *(const uint32_t*)&Bs[nr];
                    bh[j][1] = *(const uint32_t*)&Bs[nr + 8];
                    bl[j][0] = *(const uint32_t*)&Bls[nr];
                    bl[j][1] = *(const uint32_t*)&Bls[nr + 8];
                }
                // three term passes, 8 independent accumulators each
#pragma unroll
                for (int mt = 0; mt < 2; mt++)
#pragma unroll
                    for (int j = 0; j < 4; j++)
                        MMA_BF16(acc[mt][g*4+j], ah[mt][0],ah[mt][1],ah[mt][2],ah[mt][3],
                                 bh[j][0], bh[j][1]);
#pragma unroll
                for (int mt = 0; mt < 2; mt++)
#pragma unroll
                    for (int j = 0; j < 4; j++)
                        MMA_BF16(acc[mt][g*4+j], ah[mt][0],ah[mt][1],ah[mt][2],ah[mt][3],
                                 bl[j][0], bl[j][1]);
#pragma unroll
                for (int mt = 0; mt < 2; mt++)
#pragma unroll
                    for (int j = 0; j < 4; j++)
                        MMA_BF16(acc[mt][g*4+j], al[mt][0],al[mt][1],al[mt][2],al[mt][3],
                                 bh[j][0], bh[j][1]);
            }
        }
        __syncthreads();
    }

    // ---------------- epilogue ----------------
#pragma unroll
    for (int mt = 0; mt < 2; mt++) {
        int r0 = bm * 128 + warp_m * 32 + mt * 16 + qr;
#pragma unroll
        for (int nt = 0; nt < 8; nt++) {
            int c = bn * 128 + warp_n * 64 + nt * 8 + qc * 2;
            const float* a = acc[mt][nt];
#pragma unroll
            for (int rr = 0; rr < 2; rr++) {
                int r = r0 + rr * 8;
                float v0 = a[rr * 2 + 0], v1 = a[rr * 2 + 1];
                if (MODE == 0) {
                    float* C = g_zx + (size_t)z * ZXSZ + (size_t)r * NPROJ2;
                    float vv[2] = {v0, v1};
#pragma unroll
                    for (int h = 0; h < 2; h++) {
                        int cc = c + h;
                        if (cc < NPROJ2) {
                            int dI = (cc >= DPROJ);
                            int rI = cc - dI * DPROJ;
                            float o;
                            if (rI < 2 * DINN + 2 * NSS) o = siluf(vv[h]);
                            else {
                                const float* dtb = z ? (dI ? dtbV1 : dtbV0)
                                                     : (dI ? dtbH1 : dtbH0);
                                o = softplusf(vv[h] + dtb[rI - (2 * DINN + 2 * NSS)]);
                            }
                            C[cc] = o;
                        }
                    }
                } else if (MODE == 1) {
                    int orow = r;
                    if (z >= 2) orow = (r & ~(LL - 1)) | rowmap[r];
                    size_t rb = (size_t)orow * 1024 + z * 256 + c;
                    float o0 = siluf(v0), o1 = siluf(v1);
                    __nv_bfloat16 h0, l0, h1, l1;
                    split_bf16(o0, h0, l0); split_bf16(o1, h1, l1);
                    __nv_bfloat162 ph; ph.x = h0; ph.y = h1;
                    __nv_bfloat162 pl; pl.x = l0; pl.y = l1;
                    *(__nv_bfloat162*)&g_cat_hi[rb] = ph;
                    *(__nv_bfloat162*)&g_cat_lo[rb] = pl;
                } else {
                    float2 o; o.x = v0; o.y = v1;
                    *(float2*)&Cext[(size_t)r * 256 + c] = o;
                }
            }
        }
    }
}

// ---------------- scan kernels ----------------
struct SP { const float* alog[4]; const float* Dp[4]; };

__global__ __launch_bounds__(64) void scan_pass1(SP sp)
{
    __shared__ float bc[QC][20];
    __shared__ float xs[SUBC][HPP];

    int chunk = blockIdx.x;
    int b = blockIdx.y >> 2, head = blockIdx.y & 3, dir = blockIdx.z;
    int tid = threadIdx.x;

    const float* base = g_zx + (size_t)(dir >> 1) * ZXSZ;
    int off = (dir & 1) * DPROJ;
    bool rev = (dir & 1);
    long t0 = rev ? (long)(LL - 1 - chunk * QC) : (long)(chunk * QC);
    long rstride = rev ? -(long)NPROJ2 : (long)NPROJ2;
    const float* row0 = base + ((long)b * LL + t0) * NPROJ2 + off;

    for (int idx = tid; idx < QC * 20; idx += 64) {
        int st = idx / 20, q = idx - st * 20;
        bc[st][q] = row0[(long)st * rstride + 2 * DINN + q];
    }

    float a = -__expf(sp.alog[dir][head]);
    float s[NSS];
#pragma unroll
    for (int n = 0; n < NSS; n++) s[n] = 0.f;
    float Pd = 1.f;

    const float* xbase = row0 + DINN + head * HPP;
    for (int sub = 0; sub < QC; sub += SUBC) {
        __syncthreads();
        for (int idx = tid; idx < SUBC * 16; idx += 64) {
            int st = idx >> 4, v = (idx & 15) * 4;
            *(float4*)&xs[st][v] = *(const float4*)(xbase + (long)(sub + st) * rstride + v);
        }
        __syncthreads();
        for (int st = 0; st < SUBC; st++) {
            int t = sub + st;
            float dt = bc[t][16 + head];
            float dA = __expf(dt * a);
            float dtx = dt * xs[st][tid];
            Pd *= dA;
            float4 b0 = *(const float4*)&bc[t][0];
            float4 b1 = *(const float4*)&bc[t][4];
            s[0] = fmaf(dA, s[0], b0.x * dtx);
            s[1] = fmaf(dA, s[1], b0.y * dtx);
            s[2] = fmaf(dA, s[2], b0.z * dtx);
            s[3] = fmaf(dA, s[3], b0.w * dtx);
            s[4] = fmaf(dA, s[4], b1.x * dtx);
            s[5] = fmaf(dA, s[5], b1.y * dtx);
            s[6] = fmaf(dA, s[6], b1.z * dtx);
            s[7] = fmaf(dA, s[7], b1.w * dtx);
        }
    }

    int u = (dir * BB + b) * NHH + head;
    size_t sb = ((size_t)u * NCHUNK + chunk) * (HPP * NSS) + (size_t)tid * NSS;
#pragma unroll
    for (int n = 0; n < NSS; n++) g_cstate[sb + n] = s[n];
    if (tid == 0) g_cdecay[u * NCHUNK + chunk] = Pd;
}

__global__ __launch_bounds__(512) void scan_pass2()
{
    __shared__ float dec[NCHUNK];
    int u = blockIdx.x, tid = threadIdx.x;
    if (tid < NCHUNK) dec[tid] = g_cdecay[u * NCHUNK + tid];
    __syncthreads();
    float h = 0.f;
    size_t base = (size_t)u * NCHUNK * (HPP * NSS) + tid;
    for (int cb = 0; cb < NCHUNK / 8; cb++) {
        float v[8];
#pragma unroll
        for (int j = 0; j < 8; j++)
            v[j] = g_cstate[base + (size_t)(cb * 8 + j) * (HPP * NSS)];
#pragma unroll
        for (int j = 0; j < 8; j++) {
            size_t idx = base + (size_t)(cb * 8 + j) * (HPP * NSS);
            g_istate[idx] = h;
            h = dec[cb * 8 + j] * h + v[j];
        }
    }
}

__global__ __launch_bounds__(64) void scan_pass3(SP sp)
{
    __shared__ float bc[QC][20];
    __shared__ float xs[SUBC][HPP];
    __shared__ float zs[SUBC][HPP];

    int chunk = blockIdx.x;
    int b = blockIdx.y >> 2, head = blockIdx.y & 3, dir = blockIdx.z;
    int tid = threadIdx.x;

    const float* base = g_zx + (size_t)(dir >> 1) * ZXSZ;
    int off = (dir & 1) * DPROJ;
    bool rev = (dir & 1);
    long t0 = rev ? (long)(LL - 1 - chunk * QC) : (long)(chunk * QC);
    long rstride = rev ? -(long)NPROJ2 : (long)NPROJ2;
    const float* row0 = base + ((long)b * LL + t0) * NPROJ2 + off;

    for (int idx = tid; idx < QC * 20; idx += 64) {
        int st = idx / 20, q = idx - st * 20;
        bc[st][q] = row0[(long)st * rstride + 2 * DINN + q];
    }

    float a = -__expf(sp.alog[dir][head]);
    float Dh = sp.Dp[dir][head];

    int u = (dir * BB + b) * NHH + head;
    size_t sb = ((size_t)u * NCHUNK + chunk) * (HPP * NSS) + (size_t)tid * NSS;
    float s[NSS];
#pragma unroll
    for (int n = 0; n < NSS; n++) s[n] = g_istate[sb + n];

    size_t ybase = (size_t)dir * YSZ + ((size_t)b * LL + (size_t)t0) * DINN + head * HPP + tid;
    long ystride = rev ? -(long)DINN : (long)DINN;

    const float* xbase = row0 + DINN + head * HPP;
    const float* zbase = row0 + head * HPP;

    for (int sub = 0; sub < QC; sub += SUBC) {
        __syncthreads();
        for (int idx = tid; idx < SUBC * 16; idx += 64) {
            int st = idx >> 4, v = (idx & 15) * 4;
            *(float4*)&xs[st][v] = *(const float4*)(xbase + (long)(sub + st) * rstride + v);
            *(float4*)&zs[st][v] = *(const float4*)(zbase + (long)(sub + st) * rstride + v);
        }
        __syncthreads();
        for (int st = 0; st < SUBC; st++) {
            int t = sub + st;
            float dt = bc[t][16 + head];
            float dA = __expf(dt * a);
            float xv = xs[st][tid];
            float dtx = dt * xv;
            float4 b0 = *(const float4*)&bc[t][0];
            float4 b1 = *(const float4*)&bc[t][4];
            float4 c0 = *(const float4*)&bc[t][8];
            float4 c1 = *(const float4*)&bc[t][12];
            s[0] = fmaf(dA, s[0], b0.x * dtx);
            s[1] = fmaf(dA, s[1], b0.y * dtx);
            s[2] = fmaf(dA, s[2], b0.z * dtx);
            s[3] = fmaf(dA, s[3], b0.w * dtx);
            s[4] = fmaf(dA, s[4], b1.x * dtx);
            s[5] = fmaf(dA, s[5], b1.y * dtx);
            s[6] = fmaf(dA, s[6], b1.z * dtx);
            s[7] = fmaf(dA, s[7], b1.w * dtx);
            float y0 = fmaf(s[0], c0.x, fmaf(s[2], c0.z, fmaf(s[4], c1.x, s[6] * c1.z)));
            float y1 = fmaf(s[1], c0.y, fmaf(s[3], c0.w, fmaf(s[5], c1.y, s[7] * c1.w)));
            float outv = fmaf(Dh, xv, y0 + y1) * zs[st][tid];
            __nv_bfloat16 h, l; split_bf16(outv, h, l);
            size_t yo = ybase + (long)t * ystride;
            g_y_hi[yo] = h;
            g_y_lo[yo] = l;
        }
    }
}

// ---------------- launch ----------------
extern "C" void kernel_launch(void* const* d_in, const int* in_sizes, int n_in,
                              void* d_out, int out_size)
{
    const float *xH, *xV, *WinH, *WinV, *WoHF, *WoHB, *WoVF, *WoVB, *Wout;
    const float *dtb[4], *alog[4], *Dp[4];
    const int* v2h;

    if (in_sizes[0] == 4) {
        alog[1] = (const float*)d_in[0];  alog[0] = (const float*)d_in[1];
        alog[3] = (const float*)d_in[2];  alog[2] = (const float*)d_in[3];
        Dp[1]   = (const float*)d_in[4];  Dp[0]   = (const float*)d_in[5];
        Dp[3]   = (const float*)d_in[6];  Dp[2]   = (const float*)d_in[7];
        WinH = (const float*)d_in[8];     WinV = (const float*)d_in[9];
        Wout = (const float*)d_in[10];
        WoHB = (const float*)d_in[11];    WoHF = (const float*)d_in[12];
        WoVB = (const float*)d_in[13];    WoVF = (const float*)d_in[14];
        dtb[1] = (const float*)d_in[15];  dtb[0] = (const float*)d_in[16];
        dtb[3] = (const float*)d_in[17];  dtb[2] = (const float*)d_in[18];
        v2h = (const int*)d_in[19];
        xH = (const float*)d_in[20];      xV = (const float*)d_in[21];
    } else if (in_sizes[4] == 65536) {
        xH = (const float*)d_in[0];  xV = (const float*)d_in[1];
        WinH = (const float*)d_in[2]; WinV = (const float*)d_in[3];
        WoHF = (const float*)d_in[4]; WoHB = (const float*)d_in[5];
        WoVF = (const float*)d_in[6]; WoVB = (const float*)d_in[7];
        Wout = (const float*)d_in[8];
        for (int d = 0; d < 4; d++) {
            dtb[d]  = (const float*)d_in[9 + 3 * d + 0];
            alog[d] = (const float*)d_in[9 + 3 * d + 1];
            Dp[d]   = (const float*)d_in[9 + 3 * d + 2];
        }
        v2h = (const int*)d_in[21];
    } else {
        xH = (const float*)d_in[0];  xV = (const float*)d_in[1];
        WinH = (const float*)d_in[2]; WinV = (const float*)d_in[3];
        for (int d = 0; d < 4; d++) {
            dtb[d]  = (const float*)d_in[4 + d];
            alog[d] = (const float*)d_in[8 + d];
            Dp[d]   = (const float*)d_in[12 + d];
        }
        WoHF = (const float*)d_in[16]; WoHB = (const float*)d_in[17];
        WoVF = (const float*)d_in[18]; WoVB = (const float*)d_in[19];
        Wout = (const float*)d_in[20];
        v2h = (const int*)d_in[21];
    }

    SP sp;
    for (int d = 0; d < 4; d++) { sp.alog[d] = alog[d]; sp.Dp[d] = Dp[d]; }

    cudaFuncSetAttribute(gemm_mma<0>, cudaFuncAttributeMaxDynamicSharedMemorySize, GSMEM);
    cudaFuncSetAttribute(gemm_mma<1>, cudaFuncAttributeMaxDynamicSharedMemorySize, GSMEM);
    cudaFuncSetAttribute(gemm_mma<2>, cudaFuncAttributeMaxDynamicSharedMemorySize, GSMEM);

    // launches 0-4: prep needed by gemm<0> (ordering keeps gemm<0> at launch
    // index 5 so ncu -s 5 -c 1 profiles the dominant GEMM)
    conv_split<<<(int)(AXSZ / 4 / 256), 256>>>(xH, 0);
    conv_split<<<(int)(AXSZ / 4 / 256), 256>>>(xV, 1);
    wsplit<<<1152, 256>>>(WinH, 0, 0, 256, NPROJ2, 1152);
    wsplit<<<1152, 256>>>(WinV, 0, 1, 256, NPROJ2, 1152);
    wsplit<<<1024, 256>>>(Wout, 2, 0, 1024, 256, 256);

    // launch 5: in-proj (H and V batched via z) + fused activations
    gemm_mma<0><<<dim3(9, MM / 128, 2), 256, GSMEM>>>(
        nullptr, dtb[0], dtb[1], dtb[2], dtb[3], nullptr);

    // remaining weight prep
    wsplit<<<256, 256>>>(WoHF, 1, 0, 256, 256, 256);
    wsplit<<<256, 256>>>(WoHB, 1, 1, 256, 256, 256);
    wsplit<<<256, 256>>>(WoVF, 1, 2, 256, 256, 256);
    wsplit<<<256, 256>>>(WoVB, 1, 3, 256, 256, 256);

    // chunked selective scan
    scan_pass1<<<dim3(NCHUNK, BB * NHH, 4), 64>>>(sp);
    scan_pass2<<<NUNIT, 512>>>();
    scan_pass3<<<dim3(NCHUNK, BB * NHH, 4), 64>>>(sp);

    // out-projections (all 4 dirs batched via z): silu + v2h scatter -> cat hi/lo
    gemm_mma<1><<<dim3(2, MM / 128, 4), 256, GSMEM>>>(
        nullptr, nullptr, nullptr, nullptr, nullptr, v2h);

    // final projection
    gemm_mma<2><<<dim3(2, MM / 128, 1), 256, GSMEM>>>(
        (float*)d_out, nullptr, nullptr, nullptr, nullptr, nullptr);
}